// round 13
// baseline (speedup 1.0000x reference)
#include <cuda_runtime.h>
#include <math.h>

// ---------------- problem constants ----------------
#define HW    2816          // 32*88
#define H_    32
#define W_    88
#define CIN   512
#define EMB   256
#define DNUM  325
#define XN    256
#define YN    128
#define ZN    10
#define YX    32768         // 128*256

// output layout (floats): embeds2d | embeds3d | feat | map_b
#define OFF_E2D  0
#define OFF_E3D  720896
#define OFF_FEAT 9109504
#define OFF_MAPB 9830400

// ---------------- device scratch (constants) ----------------
__device__ float g_A[EMB * 3];   // w_pe1 @ w_pe0
__device__ float g_c[EMB];       // w_pe1 @ b_pe0 + b_pe1
__device__ float g_M[16];        // inv(ego44)

// =====================================================================
// K0: constants. 1 block, 256 threads.
// =====================================================================
__global__ void k_const(const float* __restrict__ ego,
                        const float* __restrict__ w_pe0,
                        const float* __restrict__ b_pe0,
                        const float* __restrict__ w_pe1,
                        const float* __restrict__ b_pe1) {
    int o = threadIdx.x;
    float a0 = 0.f, a1 = 0.f, a2 = 0.f, c = 0.f;
#pragma unroll 8
    for (int e = 0; e < 64; e++) {
        float w1 = w_pe1[o * 64 + e];
        a0 += w1 * w_pe0[e * 3 + 0];
        a1 += w1 * w_pe0[e * 3 + 1];
        a2 += w1 * w_pe0[e * 3 + 2];
        c  += w1 * b_pe0[e];
    }
    g_A[o * 3 + 0] = a0;
    g_A[o * 3 + 1] = a1;
    g_A[o * 3 + 2] = a2;
    g_c[o] = c + b_pe1[o];

    if (o == 0) {
        // 4x4 inverse via Gauss-Jordan with partial pivoting (double).
        double m[4][8];
        for (int i = 0; i < 4; i++)
            for (int j = 0; j < 8; j++) m[i][j] = 0.0;
        for (int i = 0; i < 3; i++)
            for (int j = 0; j < 4; j++) m[i][j] = (double)ego[i * 4 + j];
        m[3][3] = 1.0;
        for (int i = 0; i < 4; i++) m[i][4 + i] = 1.0;
        for (int col = 0; col < 4; col++) {
            int piv = col;
            double best = fabs(m[col][col]);
            for (int r = col + 1; r < 4; r++) {
                double v = fabs(m[r][col]);
                if (v > best) { best = v; piv = r; }
            }
            if (piv != col)
                for (int j = 0; j < 8; j++) {
                    double t = m[col][j]; m[col][j] = m[piv][j]; m[piv][j] = t;
                }
            double inv = 1.0 / m[col][col];
            for (int j = 0; j < 8; j++) m[col][j] *= inv;
            for (int r = 0; r < 4; r++) {
                if (r == col) continue;
                double f = m[r][col];
                for (int j = 0; j < 8; j++) m[r][j] -= f * m[col][j];
            }
        }
        for (int i = 0; i < 4; i++)
            for (int j = 0; j < 4; j++) g_M[i * 4 + j] = (float)m[i][4 + j];
    }
}

// =====================================================================
// K1: feat = w_in(256x512) @ img(512x2816) + b_in. Tiled GEMM 64x64x16,
// 4x4 per thread, smem ping-pong double buffering.
// =====================================================================
#define BM 64
#define BN 64
#define BK 16
#define LDT 68   // padded smem row stride (floats), 272B -> 16B aligned

__global__ __launch_bounds__(256) void k_feat(const float* __restrict__ w_in,
                                              const float* __restrict__ b_in,
                                              const float* __restrict__ img,
                                              float* __restrict__ feat) {
    __shared__ __align__(16) float As[2][BK][LDT];
    __shared__ __align__(16) float Bs[2][BK][LDT];

    int tid = threadIdx.x;
    int bn = blockIdx.x * BN;
    int bm = blockIdx.y * BM;
    int tx = tid & 15, ty = tid >> 4;

    int a_o  = tid >> 2;        // 0..63  (output row within tile)
    int a_c4 = (tid & 3) * 4;   // k sub-offset
    int b_c  = tid >> 4;        // 0..15  (k row)
    int b_p  = (tid & 15) * 4;  // pixel sub-offset

    const float* aptr = w_in + (bm + a_o) * CIN + a_c4;
    const float* bptr = img + b_c * HW + bn + b_p;

    float4 ra = *(const float4*)aptr;
    float4 rb = *(const float4*)bptr;
    As[0][a_c4 + 0][a_o] = ra.x;
    As[0][a_c4 + 1][a_o] = ra.y;
    As[0][a_c4 + 2][a_o] = ra.z;
    As[0][a_c4 + 3][a_o] = ra.w;
    *(float4*)&Bs[0][b_c][b_p] = rb;
    __syncthreads();

    float acc[4][4] = {};
    int buf = 0;
    const int KT = CIN / BK;  // 32
    for (int kt = 0; kt < KT; kt++) {
        if (kt + 1 < KT) {
            ra = *(const float4*)(aptr + (kt + 1) * BK);
            rb = *(const float4*)(bptr + (size_t)(kt + 1) * BK * HW);
        }
#pragma unroll
        for (int k = 0; k < BK; k++) {
            float av[4], bv[4];
#pragma unroll
            for (int i = 0; i < 4; i++) av[i] = As[buf][k][ty * 4 + i];
#pragma unroll
            for (int j = 0; j < 4; j++) bv[j] = Bs[buf][k][tx * 4 + j];
#pragma unroll
            for (int i = 0; i < 4; i++)
#pragma unroll
                for (int j = 0; j < 4; j++) acc[i][j] += av[i] * bv[j];
        }
        if (kt + 1 < KT) {
            int nb = buf ^ 1;
            As[nb][a_c4 + 0][a_o] = ra.x;
            As[nb][a_c4 + 1][a_o] = ra.y;
            As[nb][a_c4 + 2][a_o] = ra.z;
            As[nb][a_c4 + 3][a_o] = ra.w;
            *(float4*)&Bs[nb][b_c][b_p] = rb;
            __syncthreads();
            buf = nb;
        }
    }
#pragma unroll
    for (int i = 0; i < 4; i++) {
        int o = bm + ty * 4 + i;
        float bi = b_in[o];
        float4 v = make_float4(acc[i][0] + bi, acc[i][1] + bi,
                               acc[i][2] + bi, acc[i][3] + bi);
        *(float4*)&feat[(size_t)o * HW + bn + tx * 4] = v;
    }
}

// =====================================================================
// K2: 2D branch. 88 blocks x 256 threads, 32 pixels/block, 2 pixels/thread.
// logits(325) GEMM from smem feat tile, softmax -> dbar -> embeds2d.
// =====================================================================
__device__ __forceinline__ float decode_scalar(unsigned u) {
    // python int -> small int bits; float32 -> normal float bits
    return (u < (1u << 26)) ? (float)(int)u : __uint_as_float(u);
}

__global__ __launch_bounds__(256) void k_2d(const float* __restrict__ feat,
                                            const float* __restrict__ w_d,
                                            const float* __restrict__ b_d,
                                            const unsigned* __restrict__ padh_p,
                                            const unsigned* __restrict__ padw_p,
                                            float* __restrict__ out2d) {
    __shared__ float Fs[256 * 32];
    __shared__ float Rm[16 * 32], Rs[16 * 32], Rw[16 * 32];
    __shared__ float Mx[32], Db[32];

    int tid = threadIdx.x;
    int tx = tid & 15, ty = tid >> 4;
    int p0 = blockIdx.x * 32;

    // load feat tile (E=256 x 32 pixels), coalesced over pixels
    {
        int e0 = tid >> 5;        // 0..7
        int px = tid & 31;
        for (int eb = 0; eb < 256; eb += 8)
            Fs[(eb + e0) * 32 + px] = feat[(size_t)(eb + e0) * HW + p0 + px];
    }
    __syncthreads();

    // depth logits: rows ty + 16*r (r<21), two pixels per thread
    float acc0[21], acc1[21];
#pragma unroll
    for (int r = 0; r < 21; r++) {
        int row = ty + 16 * r;
        float b = (row < DNUM) ? b_d[row] : -1e30f;
        acc0[r] = b;
        acc1[r] = b;
    }
#pragma unroll 2
    for (int e = 0; e < 256; e += 4) {
        float f00 = Fs[(e + 0) * 32 + tx];
        float f01 = Fs[(e + 1) * 32 + tx];
        float f02 = Fs[(e + 2) * 32 + tx];
        float f03 = Fs[(e + 3) * 32 + tx];
        float f10 = Fs[(e + 0) * 32 + tx + 16];
        float f11 = Fs[(e + 1) * 32 + tx + 16];
        float f12 = Fs[(e + 2) * 32 + tx + 16];
        float f13 = Fs[(e + 3) * 32 + tx + 16];
#pragma unroll
        for (int r = 0; r < 21; r++) {
            int row = ty + 16 * r;
            if (row < DNUM) {
                float4 w = *(const float4*)(w_d + (size_t)row * 256 + e);
                acc0[r] += w.x * f00 + w.y * f01 + w.z * f02 + w.w * f03;
                acc1[r] += w.x * f10 + w.y * f11 + w.z * f12 + w.w * f13;
            }
        }
    }

    // ---- softmax reduction over D across the 16 ty threads ----
    float m0 = -1e30f, m1 = -1e30f;
#pragma unroll
    for (int r = 0; r < 21; r++) {
        m0 = fmaxf(m0, acc0[r]);
        m1 = fmaxf(m1, acc1[r]);
    }
    Rm[ty * 32 + tx] = m0;
    Rm[ty * 32 + tx + 16] = m1;
    __syncthreads();
    if (ty == 0) {
#pragma unroll
        for (int pp = 0; pp < 2; pp++) {
            int col = tx + pp * 16;
            float m = Rm[col];
            for (int r = 1; r < 16; r++) m = fmaxf(m, Rm[r * 32 + col]);
            Mx[col] = m;
        }
    }
    __syncthreads();
    float mx0 = Mx[tx], mx1 = Mx[tx + 16];
    float s0 = 0.f, w0 = 0.f, s1 = 0.f, w1 = 0.f;
#pragma unroll
    for (int r = 0; r < 21; r++) {
        float cd = 3.0f + 0.2f * (float)(ty + 16 * r);
        float e0 = expf(acc0[r] - mx0);
        float e1 = expf(acc1[r] - mx1);
        s0 += e0; w0 += e0 * cd;
        s1 += e1; w1 += e1 * cd;
    }
    Rs[ty * 32 + tx] = s0;      Rw[ty * 32 + tx] = w0;
    Rs[ty * 32 + tx + 16] = s1; Rw[ty * 32 + tx + 16] = w1;
    __syncthreads();
    if (ty == 0) {
#pragma unroll
        for (int pp = 0; pp < 2; pp++) {
            int col = tx + pp * 16;
            float S = 0.f, Wt = 0.f;
            for (int r = 0; r < 16; r++) {
                S += Rs[r * 32 + col];
                Wt += Rw[r * 32 + col];
            }
            Db[col] = Wt / S;   // expected depth cd
        }
    }
    __syncthreads();

    // ---- embeds2d epilogue ----
    float pad_h = decode_scalar(*padh_p);
    float pad_w = decode_scalar(*padw_p);

#pragma unroll
    for (int pi = 0; pi < 2; pi++) {
        int px = tx + pi * 16;
        int p = p0 + px;
        int h = p / W_, w = p % W_;
        float cw = (float)w * pad_w / (float)W_;
        float ch = (float)h * pad_h / (float)H_;
        float db = Db[px];
        float pb0 = (g_M[0] * cw + g_M[1] * ch + g_M[2])  * db + g_M[3];
        float pb1 = (g_M[4] * cw + g_M[5] * ch + g_M[6])  * db + g_M[7];
        float pb2 = (g_M[8] * cw + g_M[9] * ch + g_M[10]) * db + g_M[11];
#pragma unroll
        for (int k = 0; k < 16; k++) {
            int o = ty + 16 * k;
            float v = g_A[o * 3 + 0] * pb0 + g_A[o * 3 + 1] * pb1 +
                      g_A[o * 3 + 2] * pb2 + g_c[o];
            out2d[(size_t)o * HW + p] = v;
        }
    }
}

// =====================================================================
// K3: 3D branch. 128 blocks (one per y) x 256 threads (one per x).
// Fused: map_b copy + height logits + softmax -> zbar + embeds3d.
// =====================================================================
__global__ __launch_bounds__(256) void k_3d(const float* __restrict__ map,
                                            const float* __restrict__ w_z,
                                            const float* __restrict__ b_z,
                                            float* __restrict__ mapb,
                                            float* __restrict__ out3d) {
    __shared__ float Wz[ZN][256];
    __shared__ __align__(16) float Av[EMB * 4];  // A0,A1,A2,c per o

    int tid = threadIdx.x;
    int y = blockIdx.x;

    for (int i = tid; i < ZN * 256; i += 256) Wz[i / 256][i % 256] = w_z[i];
    Av[tid * 4 + 0] = g_A[tid * 3 + 0];
    Av[tid * 4 + 1] = g_A[tid * 3 + 1];
    Av[tid * 4 + 2] = g_A[tid * 3 + 2];
    Av[tid * 4 + 3] = g_c[tid];
    __syncthreads();

    float acc[ZN];
#pragma unroll
    for (int z = 0; z < ZN; z++) acc[z] = b_z[z];

    int base = y * 256 + tid;
#pragma unroll 4
    for (int e = 0; e < 256; e++) {
        float v = map[(size_t)e * YX + base];
        mapb[(size_t)e * YX + base] = v;
#pragma unroll
        for (int z = 0; z < ZN; z++) acc[z] += Wz[z][e] * v;
    }

    float m = acc[0];
#pragma unroll
    for (int z = 1; z < ZN; z++) m = fmaxf(m, acc[z]);
    float s = 0.f, wsum = 0.f;
#pragma unroll
    for (int z = 0; z < ZN; z++) {
        float ez = expf(acc[z] - m);
        s += ez;
        wsum += ez * (-1.0f + 0.2f * (float)z);
    }
    float zbar = wsum / s;

    float cyf = -15.0f + 0.234375f * (float)(YN - 1 - y);  // Y-flip
    float cxv = 5.0f + 0.234375f * (float)tid;

#pragma unroll 4
    for (int o = 0; o < EMB; o++) {
        float4 a = *(const float4*)&Av[o * 4];
        out3d[(size_t)o * YX + base] = a.x * cxv + a.y * cyf + a.z * zbar + a.w;
    }
}

// =====================================================================
// launch
// =====================================================================
extern "C" void kernel_launch(void* const* d_in, const int* in_sizes, int n_in,
                              void* d_out, int out_size) {
    const float*    img   = (const float*)d_in[0];
    const float*    ego   = (const float*)d_in[1];
    const unsigned* ph    = (const unsigned*)d_in[2];
    const unsigned* pw    = (const unsigned*)d_in[3];
    const float*    w_in  = (const float*)d_in[4];
    const float*    b_in  = (const float*)d_in[5];
    const float*    w_d   = (const float*)d_in[6];
    const float*    b_d   = (const float*)d_in[7];
    const float*    w_z   = (const float*)d_in[8];
    const float*    b_z   = (const float*)d_in[9];
    const float*    w_pe0 = (const float*)d_in[10];
    const float*    b_pe0 = (const float*)d_in[11];
    const float*    w_pe1 = (const float*)d_in[12];
    const float*    b_pe1 = (const float*)d_in[13];
    const float*    map   = (const float*)d_in[14];
    float* out = (float*)d_out;

    k_const<<<1, 256>>>(ego, w_pe0, b_pe0, w_pe1, b_pe1);
    k_feat<<<dim3(44, 4), 256>>>(w_in, b_in, img, out + OFF_FEAT);
    k_3d<<<128, 256>>>(map, w_z, b_z, out + OFF_MAPB, out + OFF_E3D);
    k_2d<<<88, 256>>>(out + OFF_FEAT, w_d, b_d, ph, pw, out + OFF_E2D);
}

// round 14
// speedup vs baseline: 1.0037x; 1.0037x over previous
#include <cuda_runtime.h>
#include <math.h>

// ---------------- problem constants ----------------
#define HW    2816          // 32*88
#define H_    32
#define W_    88
#define CIN   512
#define EMB   256
#define DNUM  325
#define XN    256
#define YN    128
#define ZN    10
#define YX    32768         // 128*256

// output layout (floats): embeds2d | embeds3d | feat | map_b
#define OFF_E2D  0
#define OFF_E3D  720896
#define OFF_FEAT 9109504
#define OFF_MAPB 9830400

// ---------------- device scratch (constants) ----------------
__device__ float g_A[EMB * 3];   // w_pe1 @ w_pe0
__device__ float g_c[EMB];       // w_pe1 @ b_pe0 + b_pe1
__device__ float g_M[16];        // inv(ego44)

// =====================================================================
// K0: constants. 1 block, 256 threads.
// =====================================================================
__global__ void k_const(const float* __restrict__ ego,
                        const float* __restrict__ w_pe0,
                        const float* __restrict__ b_pe0,
                        const float* __restrict__ w_pe1,
                        const float* __restrict__ b_pe1) {
    int o = threadIdx.x;
    float a0 = 0.f, a1 = 0.f, a2 = 0.f, c = 0.f;
#pragma unroll 8
    for (int e = 0; e < 64; e++) {
        float w1 = w_pe1[o * 64 + e];
        a0 += w1 * w_pe0[e * 3 + 0];
        a1 += w1 * w_pe0[e * 3 + 1];
        a2 += w1 * w_pe0[e * 3 + 2];
        c  += w1 * b_pe0[e];
    }
    g_A[o * 3 + 0] = a0;
    g_A[o * 3 + 1] = a1;
    g_A[o * 3 + 2] = a2;
    g_c[o] = c + b_pe1[o];

    if (o == 0) {
        // 4x4 inverse via Gauss-Jordan with partial pivoting (double).
        double m[4][8];
        for (int i = 0; i < 4; i++)
            for (int j = 0; j < 8; j++) m[i][j] = 0.0;
        for (int i = 0; i < 3; i++)
            for (int j = 0; j < 4; j++) m[i][j] = (double)ego[i * 4 + j];
        m[3][3] = 1.0;
        for (int i = 0; i < 4; i++) m[i][4 + i] = 1.0;
        for (int col = 0; col < 4; col++) {
            int piv = col;
            double best = fabs(m[col][col]);
            for (int r = col + 1; r < 4; r++) {
                double v = fabs(m[r][col]);
                if (v > best) { best = v; piv = r; }
            }
            if (piv != col)
                for (int j = 0; j < 8; j++) {
                    double t = m[col][j]; m[col][j] = m[piv][j]; m[piv][j] = t;
                }
            double inv = 1.0 / m[col][col];
            for (int j = 0; j < 8; j++) m[col][j] *= inv;
            for (int r = 0; r < 4; r++) {
                if (r == col) continue;
                double f = m[r][col];
                for (int j = 0; j < 8; j++) m[r][j] -= f * m[col][j];
            }
        }
        for (int i = 0; i < 4; i++)
            for (int j = 0; j < 4; j++) g_M[i * 4 + j] = (float)m[i][4 + j];
    }
}

// =====================================================================
// K1: feat = w_in(256x512) @ img(512x2816) + b_in. Tiled GEMM 64x64x16,
// 4x4 per thread, smem ping-pong double buffering.
// =====================================================================
#define BM 64
#define BN 64
#define BK 16
#define LDT 68   // padded smem row stride (floats), 272B -> 16B aligned

__global__ __launch_bounds__(256) void k_feat(const float* __restrict__ w_in,
                                              const float* __restrict__ b_in,
                                              const float* __restrict__ img,
                                              float* __restrict__ feat) {
    __shared__ __align__(16) float As[2][BK][LDT];
    __shared__ __align__(16) float Bs[2][BK][LDT];

    int tid = threadIdx.x;
    int bn = blockIdx.x * BN;
    int bm = blockIdx.y * BM;
    int tx = tid & 15, ty = tid >> 4;

    int a_o  = tid >> 2;        // 0..63  (output row within tile)
    int a_c4 = (tid & 3) * 4;   // k sub-offset
    int b_c  = tid >> 4;        // 0..15  (k row)
    int b_p  = (tid & 15) * 4;  // pixel sub-offset

    const float* aptr = w_in + (bm + a_o) * CIN + a_c4;
    const float* bptr = img + b_c * HW + bn + b_p;

    float4 ra = *(const float4*)aptr;
    float4 rb = *(const float4*)bptr;
    As[0][a_c4 + 0][a_o] = ra.x;
    As[0][a_c4 + 1][a_o] = ra.y;
    As[0][a_c4 + 2][a_o] = ra.z;
    As[0][a_c4 + 3][a_o] = ra.w;
    *(float4*)&Bs[0][b_c][b_p] = rb;
    __syncthreads();

    float acc[4][4] = {};
    int buf = 0;
    const int KT = CIN / BK;  // 32
    for (int kt = 0; kt < KT; kt++) {
        if (kt + 1 < KT) {
            ra = *(const float4*)(aptr + (kt + 1) * BK);
            rb = *(const float4*)(bptr + (size_t)(kt + 1) * BK * HW);
        }
#pragma unroll
        for (int k = 0; k < BK; k++) {
            float av[4], bv[4];
#pragma unroll
            for (int i = 0; i < 4; i++) av[i] = As[buf][k][ty * 4 + i];
#pragma unroll
            for (int j = 0; j < 4; j++) bv[j] = Bs[buf][k][tx * 4 + j];
#pragma unroll
            for (int i = 0; i < 4; i++)
#pragma unroll
                for (int j = 0; j < 4; j++) acc[i][j] += av[i] * bv[j];
        }
        if (kt + 1 < KT) {
            int nb = buf ^ 1;
            As[nb][a_c4 + 0][a_o] = ra.x;
            As[nb][a_c4 + 1][a_o] = ra.y;
            As[nb][a_c4 + 2][a_o] = ra.z;
            As[nb][a_c4 + 3][a_o] = ra.w;
            *(float4*)&Bs[nb][b_c][b_p] = rb;
            __syncthreads();
            buf = nb;
        }
    }
#pragma unroll
    for (int i = 0; i < 4; i++) {
        int o = bm + ty * 4 + i;
        float bi = b_in[o];
        float4 v = make_float4(acc[i][0] + bi, acc[i][1] + bi,
                               acc[i][2] + bi, acc[i][3] + bi);
        *(float4*)&feat[(size_t)o * HW + bn + tx * 4] = v;
    }
}

// =====================================================================
// K2: 2D branch. 88 blocks x 256 threads, 32 pixels/block, 2 pixels/thread.
// logits(325) GEMM from smem feat tile, softmax -> dbar -> embeds2d.
// =====================================================================
__device__ __forceinline__ float decode_scalar(unsigned u) {
    // python int -> small int bits; float32 -> normal float bits
    return (u < (1u << 26)) ? (float)(int)u : __uint_as_float(u);
}

__global__ __launch_bounds__(256) void k_2d(const float* __restrict__ feat,
                                            const float* __restrict__ w_d,
                                            const float* __restrict__ b_d,
                                            const unsigned* __restrict__ padh_p,
                                            const unsigned* __restrict__ padw_p,
                                            float* __restrict__ out2d) {
    __shared__ float Fs[256 * 32];
    __shared__ float Rm[16 * 32], Rs[16 * 32], Rw[16 * 32];
    __shared__ float Mx[32], Db[32];

    int tid = threadIdx.x;
    int tx = tid & 15, ty = tid >> 4;
    int p0 = blockIdx.x * 32;

    // load feat tile (E=256 x 32 pixels), coalesced over pixels
    {
        int e0 = tid >> 5;        // 0..7
        int px = tid & 31;
        for (int eb = 0; eb < 256; eb += 8)
            Fs[(eb + e0) * 32 + px] = feat[(size_t)(eb + e0) * HW + p0 + px];
    }
    __syncthreads();

    // depth logits: rows ty + 16*r (r<21), two pixels per thread
    float acc0[21], acc1[21];
#pragma unroll
    for (int r = 0; r < 21; r++) {
        int row = ty + 16 * r;
        float b = (row < DNUM) ? b_d[row] : -1e30f;
        acc0[r] = b;
        acc1[r] = b;
    }
#pragma unroll 2
    for (int e = 0; e < 256; e += 4) {
        float f00 = Fs[(e + 0) * 32 + tx];
        float f01 = Fs[(e + 1) * 32 + tx];
        float f02 = Fs[(e + 2) * 32 + tx];
        float f03 = Fs[(e + 3) * 32 + tx];
        float f10 = Fs[(e + 0) * 32 + tx + 16];
        float f11 = Fs[(e + 1) * 32 + tx + 16];
        float f12 = Fs[(e + 2) * 32 + tx + 16];
        float f13 = Fs[(e + 3) * 32 + tx + 16];
#pragma unroll
        for (int r = 0; r < 21; r++) {
            int row = ty + 16 * r;
            if (row < DNUM) {
                float4 w = *(const float4*)(w_d + (size_t)row * 256 + e);
                acc0[r] += w.x * f00 + w.y * f01 + w.z * f02 + w.w * f03;
                acc1[r] += w.x * f10 + w.y * f11 + w.z * f12 + w.w * f13;
            }
        }
    }

    // ---- softmax reduction over D across the 16 ty threads ----
    float m0 = -1e30f, m1 = -1e30f;
#pragma unroll
    for (int r = 0; r < 21; r++) {
        m0 = fmaxf(m0, acc0[r]);
        m1 = fmaxf(m1, acc1[r]);
    }
    Rm[ty * 32 + tx] = m0;
    Rm[ty * 32 + tx + 16] = m1;
    __syncthreads();
    if (ty == 0) {
#pragma unroll
        for (int pp = 0; pp < 2; pp++) {
            int col = tx + pp * 16;
            float m = Rm[col];
            for (int r = 1; r < 16; r++) m = fmaxf(m, Rm[r * 32 + col]);
            Mx[col] = m;
        }
    }
    __syncthreads();
    float mx0 = Mx[tx], mx1 = Mx[tx + 16];
    float s0 = 0.f, w0 = 0.f, s1 = 0.f, w1 = 0.f;
#pragma unroll
    for (int r = 0; r < 21; r++) {
        float cd = 3.0f + 0.2f * (float)(ty + 16 * r);
        float e0 = expf(acc0[r] - mx0);
        float e1 = expf(acc1[r] - mx1);
        s0 += e0; w0 += e0 * cd;
        s1 += e1; w1 += e1 * cd;
    }
    Rs[ty * 32 + tx] = s0;      Rw[ty * 32 + tx] = w0;
    Rs[ty * 32 + tx + 16] = s1; Rw[ty * 32 + tx + 16] = w1;
    __syncthreads();
    if (ty == 0) {
#pragma unroll
        for (int pp = 0; pp < 2; pp++) {
            int col = tx + pp * 16;
            float S = 0.f, Wt = 0.f;
            for (int r = 0; r < 16; r++) {
                S += Rs[r * 32 + col];
                Wt += Rw[r * 32 + col];
            }
            Db[col] = Wt / S;   // expected depth cd
        }
    }
    __syncthreads();

    // ---- embeds2d epilogue ----
    float pad_h = decode_scalar(*padh_p);
    float pad_w = decode_scalar(*padw_p);

#pragma unroll
    for (int pi = 0; pi < 2; pi++) {
        int px = tx + pi * 16;
        int p = p0 + px;
        int h = p / W_, w = p % W_;
        float cw = (float)w * pad_w / (float)W_;
        float ch = (float)h * pad_h / (float)H_;
        float db = Db[px];
        float pb0 = (g_M[0] * cw + g_M[1] * ch + g_M[2])  * db + g_M[3];
        float pb1 = (g_M[4] * cw + g_M[5] * ch + g_M[6])  * db + g_M[7];
        float pb2 = (g_M[8] * cw + g_M[9] * ch + g_M[10]) * db + g_M[11];
#pragma unroll
        for (int k = 0; k < 16; k++) {
            int o = ty + 16 * k;
            float v = g_A[o * 3 + 0] * pb0 + g_A[o * 3 + 1] * pb1 +
                      g_A[o * 3 + 2] * pb2 + g_c[o];
            out2d[(size_t)o * HW + p] = v;
        }
    }
}

// =====================================================================
// K3: 3D branch. 128 blocks (one per y) x 256 threads (one per x).
// Fused: map_b copy + height logits + softmax -> zbar + embeds3d.
// =====================================================================
__global__ __launch_bounds__(256) void k_3d(const float* __restrict__ map,
                                            const float* __restrict__ w_z,
                                            const float* __restrict__ b_z,
                                            float* __restrict__ mapb,
                                            float* __restrict__ out3d) {
    __shared__ float Wz[ZN][256];
    __shared__ __align__(16) float Av[EMB * 4];  // A0,A1,A2,c per o

    int tid = threadIdx.x;
    int y = blockIdx.x;

    for (int i = tid; i < ZN * 256; i += 256) Wz[i / 256][i % 256] = w_z[i];
    Av[tid * 4 + 0] = g_A[tid * 3 + 0];
    Av[tid * 4 + 1] = g_A[tid * 3 + 1];
    Av[tid * 4 + 2] = g_A[tid * 3 + 2];
    Av[tid * 4 + 3] = g_c[tid];
    __syncthreads();

    float acc[ZN];
#pragma unroll
    for (int z = 0; z < ZN; z++) acc[z] = b_z[z];

    int base = y * 256 + tid;
#pragma unroll 4
    for (int e = 0; e < 256; e++) {
        float v = map[(size_t)e * YX + base];
        mapb[(size_t)e * YX + base] = v;
#pragma unroll
        for (int z = 0; z < ZN; z++) acc[z] += Wz[z][e] * v;
    }

    float m = acc[0];
#pragma unroll
    for (int z = 1; z < ZN; z++) m = fmaxf(m, acc[z]);
    float s = 0.f, wsum = 0.f;
#pragma unroll
    for (int z = 0; z < ZN; z++) {
        float ez = expf(acc[z] - m);
        s += ez;
        wsum += ez * (-1.0f + 0.2f * (float)z);
    }
    float zbar = wsum / s;

    float cyf = -15.0f + 0.234375f * (float)(YN - 1 - y);  // Y-flip
    float cxv = 5.0f + 0.234375f * (float)tid;

#pragma unroll 4
    for (int o = 0; o < EMB; o++) {
        float4 a = *(const float4*)&Av[o * 4];
        out3d[(size_t)o * YX + base] = a.x * cxv + a.y * cyf + a.z * zbar + a.w;
    }
}

// =====================================================================
// launch
// =====================================================================
extern "C" void kernel_launch(void* const* d_in, const int* in_sizes, int n_in,
                              void* d_out, int out_size) {
    const float*    img   = (const float*)d_in[0];
    const float*    ego   = (const float*)d_in[1];
    const unsigned* ph    = (const unsigned*)d_in[2];
    const unsigned* pw    = (const unsigned*)d_in[3];
    const float*    w_in  = (const float*)d_in[4];
    const float*    b_in  = (const float*)d_in[5];
    const float*    w_d   = (const float*)d_in[6];
    const float*    b_d   = (const float*)d_in[7];
    const float*    w_z   = (const float*)d_in[8];
    const float*    b_z   = (const float*)d_in[9];
    const float*    w_pe0 = (const float*)d_in[10];
    const float*    b_pe0 = (const float*)d_in[11];
    const float*    w_pe1 = (const float*)d_in[12];
    const float*    b_pe1 = (const float*)d_in[13];
    const float*    map   = (const float*)d_in[14];
    float* out = (float*)d_out;

    k_const<<<1, 256>>>(ego, w_pe0, b_pe0, w_pe1, b_pe1);
    k_feat<<<dim3(44, 4), 256>>>(w_in, b_in, img, out + OFF_FEAT);
    k_3d<<<128, 256>>>(map, w_z, b_z, out + OFF_MAPB, out + OFF_E3D);
    k_2d<<<88, 256>>>(out + OFF_FEAT, w_d, b_d, ph, pw, out + OFF_E2D);
}